// round 5
// baseline (speedup 1.0000x reference)
#include <cuda_runtime.h>
#include <cuda_bf16.h>
#include <math.h>

// Problem constants (fixed shapes): B=16, N=2000, C=512, H=W=7
#define Bn 16
#define Nn 2000
#define Dn 25088            // 512*7*7
#define PI2F ((float)(3.14159 / 2.0))   // matches reference constant exactly

// ---- device scratch (static allocation only; no cudaMalloc allowed) ----
__device__ float  g_dot[Bn * Nn];     // raw dots key·mem, [b][n]
__device__ float  g_mn[Nn];           // clamped memory row norms
__device__ float  g_kps[Bn * 4];      // key sum partials
__device__ float  g_kpq[Bn * 4];      // key sumsq partials
__device__ __align__(16) float2 g_w2[Nn * Bn];  // softmax weights, [n][b], duplicated (w,w)

// ---- packed fp32x2 FMA (sm_100+; ptxas will not auto-generate this) ----
__device__ __forceinline__ void fma2(unsigned long long& acc,
                                     unsigned long long a,
                                     unsigned long long b) {
    asm("fma.rn.f32x2 %0, %1, %2, %0;" : "+l"(acc) : "l"(a), "l"(b));
}
__device__ __forceinline__ float f2lo(unsigned long long v) {
    return __uint_as_float((unsigned)(v & 0xFFFFFFFFull));
}
__device__ __forceinline__ float f2hi(unsigned long long v) {
    return __uint_as_float((unsigned)(v >> 32));
}

// ============================================================
// K1: key per-sample sum & sumsq partials. grid (16, 4) x 256.
// ============================================================
__global__ void k_keystats(const float* __restrict__ key) {
    int b = blockIdx.x, p = blockIdx.y, tid = threadIdx.x;
    const float4* src = (const float4*)(key + (size_t)b * Dn);
    // D/4 = 6272 float4; quarter = 1568 float4
    float s = 0.f, q = 0.f;
    for (int i = p * 1568 + tid; i < (p + 1) * 1568; i += 256) {
        float4 v = src[i];
        s += v.x + v.y + v.z + v.w;
        q += v.x * v.x + v.y * v.y + v.z * v.z + v.w * v.w;
    }
    #pragma unroll
    for (int o = 16; o; o >>= 1) {
        s += __shfl_xor_sync(0xFFFFFFFFu, s, o);
        q += __shfl_xor_sync(0xFFFFFFFFu, q, o);
    }
    __shared__ float ss[8], sq[8];
    int w = tid >> 5;
    if ((tid & 31) == 0) { ss[w] = s; sq[w] = q; }
    __syncthreads();
    if (tid == 0) {
        float S = 0.f, Q = 0.f;
        #pragma unroll
        for (int i = 0; i < 8; ++i) { S += ss[i]; Q += sq[i]; }
        g_kps[b * 4 + p] = S;
        g_kpq[b * 4 + p] = Q;
    }
}

// =======================================================================
// K2: raw dots [16 x 2000] + memory row norms. grid 250 x 256 threads.
// Block owns 8 memory rows. Threads: bh = b-half (8 b's), g = n-quad (4 n's),
// u = d-lane (4 consecutive d's per chunk step). Key chunk (16 x 256 f32)
// staged in smem; accumulators are f32x2 packed over (even d, odd d).
// =======================================================================
__global__ __launch_bounds__(256) void k_dots(const float* __restrict__ key,
                                              const float* __restrict__ mem) {
    __shared__ __align__(16) float skey[16 * 256];
    __shared__ float sred[2][68];   // per n-quad: 64 dots + 4 sq

    int tid = threadIdx.x;
    int bh  = tid >> 7;          // 0/1 : which 8 b's
    int g   = (tid >> 6) & 1;    // 0/1 : which 4 n's
    int u   = tid & 63;          // d lane within chunk
    int nb  = blockIdx.x * 8 + g * 4;

    if (tid < 136) ((float*)sred)[tid] = 0.f;   // covered by first barrier

    unsigned long long acc[8][4];
    #pragma unroll
    for (int i = 0; i < 8; ++i)
        #pragma unroll
        for (int r = 0; r < 4; ++r) acc[i][r] = 0ull;
    unsigned long long sq2[4] = {0ull, 0ull, 0ull, 0ull};

    const float* mrow[4];
    #pragma unroll
    for (int r = 0; r < 4; ++r) mrow[r] = mem + (size_t)(nb + r) * Dn;

    for (int c = 0; c < 98; ++c) {              // 98 chunks of 256 d
        __syncthreads();
        // cooperative key chunk load: 16 rows x 64 float4
        #pragma unroll
        for (int k = 0; k < 4; ++k) {
            int e  = tid + k * 256;             // 0..1023
            int bb = e >> 6;
            int j  = e & 63;
            ((float4*)skey)[e] =
                ((const float4*)(key + (size_t)bb * Dn + c * 256))[j];
        }
        __syncthreads();

        int doff = c * 256 + u * 4;
        ulonglong2 mv[4];
        #pragma unroll
        for (int r = 0; r < 4; ++r)
            mv[r] = *(const ulonglong2*)(mrow[r] + doff);

        if (bh == 0) {
            #pragma unroll
            for (int r = 0; r < 4; ++r) {
                fma2(sq2[r], mv[r].x, mv[r].x);
                fma2(sq2[r], mv[r].y, mv[r].y);
            }
        }

        const float* kb = skey + (bh * 8) * 256 + u * 4;
        #pragma unroll
        for (int bb = 0; bb < 8; ++bb) {
            ulonglong2 kv = *(const ulonglong2*)(kb + bb * 256);
            #pragma unroll
            for (int r = 0; r < 4; ++r) {
                fma2(acc[bb][r], kv.x, mv[r].x);
                fma2(acc[bb][r], kv.y, mv[r].y);
            }
        }
    }

    // reduce across the 64 threads of each (bh, g) set
    #pragma unroll
    for (int bb = 0; bb < 8; ++bb)
        #pragma unroll
        for (int r = 0; r < 4; ++r) {
            float v = f2lo(acc[bb][r]) + f2hi(acc[bb][r]);
            #pragma unroll
            for (int o = 16; o; o >>= 1) v += __shfl_xor_sync(0xFFFFFFFFu, v, o);
            if ((tid & 31) == 0) atomicAdd(&sred[g][(bh * 8 + bb) * 4 + r], v);
        }
    if (bh == 0) {
        #pragma unroll
        for (int r = 0; r < 4; ++r) {
            float v = f2lo(sq2[r]) + f2hi(sq2[r]);
            #pragma unroll
            for (int o = 16; o; o >>= 1) v += __shfl_xor_sync(0xFFFFFFFFu, v, o);
            if ((tid & 31) == 0) atomicAdd(&sred[g][64 + r], v);
        }
    }
    __syncthreads();

    if (tid < 136) {
        int g2 = tid / 68, i = tid % 68;
        float v = sred[g2][i];
        int nbase = blockIdx.x * 8 + g2 * 4;
        if (i < 64) g_dot[(size_t)(i >> 2) * Nn + nbase + (i & 3)] = v;
        else        g_mn[nbase + (i - 64)] = fmaxf(sqrtf(v), 1e-8f);
    }
}

// ============================================================
// K3: cos -> tan -> softmax over n; write transposed duplicated
// weights (w,w). grid 16 x 256.
// ============================================================
__global__ void k_softmax() {
    int b = blockIdx.x, tid = threadIdx.x;
    __shared__ float sbuf[256];
    __shared__ float s_kfac;

    if (tid == 0) {
        float S = 0.f, Q = 0.f;
        #pragma unroll
        for (int p = 0; p < 4; ++p) { S += g_kps[b * 4 + p]; Q += g_kpq[b * 4 + p]; }
        S += 1e-7f;                                   // EPS_SUM
        // (s+eps)*kn = max(sqrt(sq_key), 1e-8*(s+eps))
        s_kfac = 1.f / fmaxf(sqrtf(Q), 1e-8f * S);
    }
    __syncthreads();
    float kf = s_kfac;

    float tv[8];
    float mx = -3.4e38f;
    #pragma unroll
    for (int i = 0; i < 8; ++i) {
        int n = tid + i * 256;
        if (n < Nn) {
            float cosv = g_dot[(size_t)b * Nn + n] * kf / g_mn[n];
            float t = tanf(cosv * PI2F);
            tv[i] = t;
            mx = fmaxf(mx, t);
        } else tv[i] = -3.4e38f;
    }
    sbuf[tid] = mx; __syncthreads();
    for (int s = 128; s; s >>= 1) {
        if (tid < s) sbuf[tid] = fmaxf(sbuf[tid], sbuf[tid + s]);
        __syncthreads();
    }
    mx = sbuf[0];
    __syncthreads();

    float sum = 0.f;
    #pragma unroll
    for (int i = 0; i < 8; ++i) {
        int n = tid + i * 256;
        if (n < Nn) { float e = expf(tv[i] - mx); tv[i] = e; sum += e; }
    }
    sbuf[tid] = sum; __syncthreads();
    for (int s = 128; s; s >>= 1) {
        if (tid < s) sbuf[tid] += sbuf[tid + s];
        __syncthreads();
    }
    float inv = 1.f / sbuf[0];

    #pragma unroll
    for (int i = 0; i < 8; ++i) {
        int n = tid + i * 256;
        if (n < Nn) {
            float w = tv[i] * inv;
            g_w2[(size_t)n * Bn + b] = make_float2(w, w);  // pre-duplicated pair
        }
    }
}

// =======================================================================
// K4: out[b][d] = sum_n w[b][n] * mem[n][d]. grid (49, 8) x 128 threads.
// Thread owns 4 consecutive d; 16 b accumulators as f32x2 pairs.
// n split 8 ways across grid.y; partials combined via atomicAdd.
// =======================================================================
__global__ __launch_bounds__(128) void k_read(const float* __restrict__ mem,
                                              float* __restrict__ out) {
    int tid = threadIdx.x;
    int d  = blockIdx.x * 512 + tid * 4;
    int n0 = blockIdx.y * 250;

    unsigned long long acc[16][2];
    #pragma unroll
    for (int b = 0; b < 16; ++b) { acc[b][0] = 0ull; acc[b][1] = 0ull; }

    const float* mp = mem + (size_t)n0 * Dn + d;
    const ulonglong2* wp = (const ulonglong2*)(g_w2 + (size_t)n0 * Bn);

    for (int n = 0; n < 250; ++n) {
        ulonglong2 mv = *(const ulonglong2*)mp;   // (d0,d1),(d2,d3)
        mp += Dn;
        #pragma unroll
        for (int q = 0; q < 8; ++q) {
            ulonglong2 wv = wp[q];                // (w2q,w2q),(w2q+1,w2q+1)
            fma2(acc[2 * q    ][0], wv.x, mv.x);
            fma2(acc[2 * q    ][1], wv.x, mv.y);
            fma2(acc[2 * q + 1][0], wv.y, mv.x);
            fma2(acc[2 * q + 1][1], wv.y, mv.y);
        }
        wp += 8;                                  // 16 float2 = 8 ulonglong2 per n
    }

    #pragma unroll
    for (int b = 0; b < 16; ++b) {
        float* o = out + (size_t)b * Dn + d;
        atomicAdd(o + 0, f2lo(acc[b][0]));
        atomicAdd(o + 1, f2hi(acc[b][0]));
        atomicAdd(o + 2, f2lo(acc[b][1]));
        atomicAdd(o + 3, f2hi(acc[b][1]));
    }
}

// ============================================================
extern "C" void kernel_launch(void* const* d_in, const int* in_sizes, int n_in,
                              void* d_out, int out_size) {
    const float* key = (const float*)d_in[0];
    const float* mem = (const float*)d_in[1];
    // metadata order is key, memory; swap defensively if sizes say otherwise
    if (n_in >= 2 && in_sizes[0] == Nn * Dn) {
        key = (const float*)d_in[1];
        mem = (const float*)d_in[0];
    }
    float* out = (float*)d_out;

    cudaMemsetAsync(d_out, 0, (size_t)out_size * sizeof(float), 0);
    k_keystats<<<dim3(16, 4), 256>>>(key);
    k_dots<<<250, 256>>>(key, mem);
    k_softmax<<<16, 256>>>();
    k_read<<<dim3(49, 8), 128>>>(mem, out);
}

// round 9
// speedup vs baseline: 1.7262x; 1.7262x over previous
#include <cuda_runtime.h>
#include <cuda_bf16.h>
#include <math.h>

// Problem constants (fixed shapes): B=16, N=2000, C=512, H=W=7
#define Bn 16
#define Nn 2000
#define Dn 25088            // 512*7*7
#define PI2F ((float)(3.14159 / 2.0))   // matches reference constant exactly
#define CHUNK 128           // floats per d-chunk in k_dots
#define NCH 196             // 25088 / 128
#define DSPLIT 4            // d-split for k_dots
#define CPB 49              // chunks per block = NCH / DSPLIT

// ---- device scratch (static allocation only; no cudaMalloc allowed) ----
__device__ float  g_dotp[DSPLIT * Bn * Nn];  // partial dots per d-split, [p][b][n]
__device__ float  g_sqp[DSPLIT * Nn];        // partial row sumsq per d-split, [p][n]
__device__ float  g_kps[Bn * 4];             // key sum partials
__device__ float  g_kpq[Bn * 4];             // key sumsq partials
__device__ __align__(16) float2 g_w2[Nn * Bn];  // weights, [n][b], duplicated (w,w)

// ---- packed fp32x2 FMA (sm_100+; ptxas will not auto-generate this) ----
__device__ __forceinline__ void fma2(unsigned long long& acc,
                                     unsigned long long a,
                                     unsigned long long b) {
    asm("fma.rn.f32x2 %0, %1, %2, %0;" : "+l"(acc) : "l"(a), "l"(b));
}
__device__ __forceinline__ float f2lo(unsigned long long v) {
    return __uint_as_float((unsigned)(v & 0xFFFFFFFFull));
}
__device__ __forceinline__ float f2hi(unsigned long long v) {
    return __uint_as_float((unsigned)(v >> 32));
}

// ============================================================
// K1: key per-sample sum & sumsq partials. grid (16, 4) x 256.
// ============================================================
__global__ void k_keystats(const float* __restrict__ key) {
    int b = blockIdx.x, p = blockIdx.y, tid = threadIdx.x;
    const float4* src = (const float4*)(key + (size_t)b * Dn);
    float s = 0.f, q = 0.f;
    for (int i = p * 1568 + tid; i < (p + 1) * 1568; i += 256) {
        float4 v = src[i];
        s += v.x + v.y + v.z + v.w;
        q += v.x * v.x + v.y * v.y + v.z * v.z + v.w * v.w;
    }
    #pragma unroll
    for (int o = 16; o; o >>= 1) {
        s += __shfl_xor_sync(0xFFFFFFFFu, s, o);
        q += __shfl_xor_sync(0xFFFFFFFFu, q, o);
    }
    __shared__ float ss[8], sq[8];
    int w = tid >> 5;
    if ((tid & 31) == 0) { ss[w] = s; sq[w] = q; }
    __syncthreads();
    if (tid == 0) {
        float S = 0.f, Q = 0.f;
        #pragma unroll
        for (int i = 0; i < 8; ++i) { S += ss[i]; Q += sq[i]; }
        g_kps[b * 4 + p] = S;
        g_kpq[b * 4 + p] = Q;
    }
}

// =======================================================================
// K2: partial dots + partial sumsq. grid (125, 4) x 256 threads.
// Block owns 16 memory rows, 49 d-chunks of 128 floats (d-split by grid.y).
// Both key chunk (16x128) and mem chunk (16x128) are double-buffered in smem.
// Lane layout per warp: bit7=bh (which 8 b's), bits[6:5]=u_hi, bits[4:3]=g
// (which 4 n's), bits[2:0]=u_lo. d-lane = u_hi*8+u_lo (4 floats each).
// g in-warp -> key LDS is a 4-way in-warp broadcast (128B served / LDS.128).
// =======================================================================
__global__ __launch_bounds__(256, 2) void k_dots(const float* __restrict__ key,
                                                 const float* __restrict__ mem) {
    __shared__ __align__(16) float skey[2][16 * CHUNK];
    __shared__ __align__(16) float smm[2][16 * CHUNK];
    __shared__ float sred[256];   // [bh][g][bb][r]
    __shared__ float ssq[16];     // [g][r]

    int tid  = threadIdx.x;
    int bh   = tid >> 7;
    int g    = (tid >> 3) & 3;
    int u_lo = tid & 7;
    int dl   = ((tid >> 5) & 3) * 8 + u_lo;   // d-lane 0..31
    int nb   = blockIdx.x * 16;
    int sy   = blockIdx.y;
    int cbase = sy * CPB;

    sred[tid] = 0.f;
    if (tid < 16) ssq[tid] = 0.f;

    unsigned long long acc[8][4];
    #pragma unroll
    for (int i = 0; i < 8; ++i)
        #pragma unroll
        for (int r = 0; r < 4; ++r) acc[i][r] = 0ull;
    unsigned long long sq2[4] = {0ull, 0ull, 0ull, 0ull};

    // cooperative staging lanes: 2 key rows + 2 mem rows per thread
    int row0 = tid >> 5;          // 0..7
    int j    = tid & 31;          // float4 within row

    const float* kr0 = key + (size_t)row0 * Dn;
    const float* kr1 = key + (size_t)(row0 + 8) * Dn;
    const float* mr0 = mem + (size_t)(nb + row0) * Dn;
    const float* mr1 = mem + (size_t)(nb + row0 + 8) * Dn;

    // prime chunk 0 into buffer 0
    {
        int off = cbase * CHUNK + j * 4;
        *(float4*)&skey[0][row0 * CHUNK + j * 4]      = *(const float4*)(kr0 + off);
        *(float4*)&skey[0][(row0 + 8) * CHUNK + j * 4] = *(const float4*)(kr1 + off);
        *(float4*)&smm[0][row0 * CHUNK + j * 4]       = *(const float4*)(mr0 + off);
        *(float4*)&smm[0][(row0 + 8) * CHUNK + j * 4]  = *(const float4*)(mr1 + off);
    }
    __syncthreads();

    for (int cc = 0; cc < CPB; ++cc) {
        int buf = cc & 1;
        float4 a0, a1, b0, b1;
        bool pre = (cc + 1 < CPB);
        if (pre) {
            int off = (cbase + cc + 1) * CHUNK + j * 4;
            a0 = *(const float4*)(kr0 + off);
            a1 = *(const float4*)(kr1 + off);
            b0 = *(const float4*)(mr0 + off);
            b1 = *(const float4*)(mr1 + off);
        }

        // compute from buf
        ulonglong2 mv[4];
        #pragma unroll
        for (int r = 0; r < 4; ++r)
            mv[r] = *(const ulonglong2*)&smm[buf][(g * 4 + r) * CHUNK + dl * 4];
        if (bh == 0) {
            #pragma unroll
            for (int r = 0; r < 4; ++r) {
                fma2(sq2[r], mv[r].x, mv[r].x);
                fma2(sq2[r], mv[r].y, mv[r].y);
            }
        }
        #pragma unroll
        for (int bb = 0; bb < 8; ++bb) {
            ulonglong2 kv = *(const ulonglong2*)&skey[buf][(bh * 8 + bb) * CHUNK + dl * 4];
            #pragma unroll
            for (int r = 0; r < 4; ++r) {
                fma2(acc[bb][r], kv.x, mv[r].x);
                fma2(acc[bb][r], kv.y, mv[r].y);
            }
        }

        if (pre) {
            int nb2 = buf ^ 1;
            *(float4*)&skey[nb2][row0 * CHUNK + j * 4]       = a0;
            *(float4*)&skey[nb2][(row0 + 8) * CHUNK + j * 4]  = a1;
            *(float4*)&smm[nb2][row0 * CHUNK + j * 4]        = b0;
            *(float4*)&smm[nb2][(row0 + 8) * CHUNK + j * 4]   = b1;
        }
        __syncthreads();
    }

    // reduce: butterfly over u_lo (8 lanes), then smem-atomic across the 4 u_hi warps
    #pragma unroll
    for (int bb = 0; bb < 8; ++bb)
        #pragma unroll
        for (int r = 0; r < 4; ++r) {
            float v = f2lo(acc[bb][r]) + f2hi(acc[bb][r]);
            v += __shfl_xor_sync(0xFFFFFFFFu, v, 1);
            v += __shfl_xor_sync(0xFFFFFFFFu, v, 2);
            v += __shfl_xor_sync(0xFFFFFFFFu, v, 4);
            if (bb == u_lo)
                atomicAdd(&sred[bh * 128 + g * 32 + bb * 4 + r], v);
        }
    if (bh == 0) {
        #pragma unroll
        for (int r = 0; r < 4; ++r) {
            float v = f2lo(sq2[r]) + f2hi(sq2[r]);
            v += __shfl_xor_sync(0xFFFFFFFFu, v, 1);
            v += __shfl_xor_sync(0xFFFFFFFFu, v, 2);
            v += __shfl_xor_sync(0xFFFFFFFFu, v, 4);
            if (u_lo == r) atomicAdd(&ssq[g * 4 + r], v);
        }
    }
    __syncthreads();

    {   // write 256 partial dots
        int r = tid & 3, bb = (tid >> 2) & 7, gg = (tid >> 5) & 3, b2 = tid >> 7;
        int b = b2 * 8 + bb, n = nb + gg * 4 + r;
        g_dotp[((size_t)sy * Bn + b) * Nn + n] = sred[tid];
    }
    if (tid < 16) {
        int r = tid & 3, gg = tid >> 2;
        g_sqp[(size_t)sy * Nn + nb + gg * 4 + r] = ssq[tid];
    }
}

// ============================================================
// K3: sum partials -> cos -> tan -> softmax; write transposed
// duplicated weights (w,w). grid 16 x 256.
// ============================================================
__global__ void k_softmax() {
    int b = blockIdx.x, tid = threadIdx.x;
    __shared__ float sbuf[256];
    __shared__ float s_kfac;

    if (tid == 0) {
        float S = 0.f, Q = 0.f;
        #pragma unroll
        for (int p = 0; p < 4; ++p) { S += g_kps[b * 4 + p]; Q += g_kpq[b * 4 + p]; }
        S += 1e-7f;                                   // EPS_SUM
        // (s+eps)*kn = max(sqrt(sq_key), 1e-8*(s+eps))
        s_kfac = 1.f / fmaxf(sqrtf(Q), 1e-8f * S);
    }
    __syncthreads();
    float kf = s_kfac;

    float tv[8];
    float mx = -3.4e38f;
    #pragma unroll
    for (int i = 0; i < 8; ++i) {
        int n = tid + i * 256;
        if (n < Nn) {
            float dot = 0.f, sqv = 0.f;
            #pragma unroll
            for (int p = 0; p < DSPLIT; ++p) {
                dot += g_dotp[((size_t)p * Bn + b) * Nn + n];
                sqv += g_sqp[(size_t)p * Nn + n];
            }
            float mn = fmaxf(sqrtf(sqv), 1e-8f);
            float cosv = dot * kf / mn;
            float t = tanf(cosv * PI2F);
            tv[i] = t;
            mx = fmaxf(mx, t);
        } else tv[i] = -3.4e38f;
    }
    sbuf[tid] = mx; __syncthreads();
    for (int s = 128; s; s >>= 1) {
        if (tid < s) sbuf[tid] = fmaxf(sbuf[tid], sbuf[tid + s]);
        __syncthreads();
    }
    mx = sbuf[0];
    __syncthreads();

    float sum = 0.f;
    #pragma unroll
    for (int i = 0; i < 8; ++i) {
        int n = tid + i * 256;
        if (n < Nn) { float e = expf(tv[i] - mx); tv[i] = e; sum += e; }
    }
    sbuf[tid] = sum; __syncthreads();
    for (int s = 128; s; s >>= 1) {
        if (tid < s) sbuf[tid] += sbuf[tid + s];
        __syncthreads();
    }
    float inv = 1.f / sbuf[0];

    #pragma unroll
    for (int i = 0; i < 8; ++i) {
        int n = tid + i * 256;
        if (n < Nn) {
            float w = tv[i] * inv;
            g_w2[(size_t)n * Bn + b] = make_float2(w, w);  // pre-duplicated pair
        }
    }
}

// =======================================================================
// K4: out[b][d] = sum_n w[b][n] * mem[n][d]. grid (49, 16) x 128 threads.
// Thread owns 4 consecutive d; 16 b accumulators as f32x2 pairs.
// n split 16 ways; weight tile (125 n x 128B) staged in smem once;
// mem row prefetched one iteration ahead. Partials combined via atomicAdd.
// =======================================================================
__global__ __launch_bounds__(128, 4) void k_read(const float* __restrict__ mem,
                                                 float* __restrict__ out) {
    __shared__ __align__(16) ulonglong2 sw[125 * 8];   // 16000 B

    int tid = threadIdx.x;
    int d   = blockIdx.x * 512 + tid * 4;
    int n0  = blockIdx.y * 125;

    // stage weight tile: 1000 x 16B
    {
        const float4* src = (const float4*)(g_w2 + (size_t)n0 * Bn);
        for (int i = tid; i < 1000; i += 128)
            ((float4*)sw)[i] = src[i];
    }

    unsigned long long acc[16][2];
    #pragma unroll
    for (int b = 0; b < 16; ++b) { acc[b][0] = 0ull; acc[b][1] = 0ull; }

    const float* mp = mem + (size_t)n0 * Dn + d;
    __syncthreads();

    ulonglong2 mv = *(const ulonglong2*)mp;
    for (int n = 0; n < 125; ++n) {
        ulonglong2 cur = mv;
        mp += Dn;
        if (n != 124) mv = *(const ulonglong2*)mp;   // prefetch next row
        const ulonglong2* wq = sw + n * 8;
        #pragma unroll
        for (int q = 0; q < 8; ++q) {
            ulonglong2 wv = wq[q];                // (w2q,w2q),(w2q+1,w2q+1)
            fma2(acc[2 * q    ][0], wv.x, cur.x);
            fma2(acc[2 * q    ][1], wv.x, cur.y);
            fma2(acc[2 * q + 1][0], wv.y, cur.x);
            fma2(acc[2 * q + 1][1], wv.y, cur.y);
        }
    }

    #pragma unroll
    for (int b = 0; b < 16; ++b) {
        float* o = out + (size_t)b * Dn + d;
        atomicAdd(o + 0, f2lo(acc[b][0]));
        atomicAdd(o + 1, f2hi(acc[b][0]));
        atomicAdd(o + 2, f2lo(acc[b][1]));
        atomicAdd(o + 3, f2hi(acc[b][1]));
    }
}

// ============================================================
extern "C" void kernel_launch(void* const* d_in, const int* in_sizes, int n_in,
                              void* d_out, int out_size) {
    const float* key = (const float*)d_in[0];
    const float* mem = (const float*)d_in[1];
    // metadata order is key, memory; swap defensively if sizes say otherwise
    if (n_in >= 2 && in_sizes[0] == Nn * Dn) {
        key = (const float*)d_in[1];
        mem = (const float*)d_in[0];
    }
    float* out = (float*)d_out;

    cudaMemsetAsync(d_out, 0, (size_t)out_size * sizeof(float), 0);
    k_keystats<<<dim3(16, 4), 256>>>(key);
    k_dots<<<dim3(125, DSPLIT), 256>>>(key, mem);
    k_softmax<<<16, 256>>>();
    k_read<<<dim3(49, 16), 128>>>(mem, out);
}

// round 10
// speedup vs baseline: 2.3337x; 1.3519x over previous
#include <cuda_runtime.h>
#include <cuda_bf16.h>
#include <math.h>

// Problem constants (fixed shapes): B=16, N=2000, C=512, H=W=7
#define Bn 16
#define Nn 2000
#define Dn 25088            // 512*7*7
#define PI2F ((float)(3.14159 / 2.0))   // matches reference constant exactly
#define CHUNK 128           // floats per d-chunk in k_dots
#define DSPLIT 7            // d-split for k_dots
#define CPB 28              // chunks per block = (25088/128)/7

// ---- device scratch (static allocation only; no cudaMalloc allowed) ----
__device__ float  g_dotp[DSPLIT * Bn * Nn];  // partial dots per d-split, [p][b][n]
__device__ float  g_sqp[DSPLIT * Nn];        // partial row sumsq per d-split, [p][n]
__device__ float  g_kps[Bn * 4];             // key sum partials
__device__ float  g_kpq[Bn * 4];             // key sumsq partials
__device__ __align__(16) float2 g_w2[Nn * Bn];  // weights, [n][b], duplicated (w,w)

// ---- packed fp32x2 FMA (sm_100+; ptxas will not auto-generate this) ----
__device__ __forceinline__ void fma2(unsigned long long& acc,
                                     unsigned long long a,
                                     unsigned long long b) {
    asm("fma.rn.f32x2 %0, %1, %2, %0;" : "+l"(acc) : "l"(a), "l"(b));
}
__device__ __forceinline__ float f2lo(unsigned long long v) {
    return __uint_as_float((unsigned)(v & 0xFFFFFFFFull));
}
__device__ __forceinline__ float f2hi(unsigned long long v) {
    return __uint_as_float((unsigned)(v >> 32));
}

// ---- cp.async (LDGSTS) helpers ----
__device__ __forceinline__ void cp16(void* smem, const void* gmem) {
    unsigned s = (unsigned)__cvta_generic_to_shared(smem);
    asm volatile("cp.async.cg.shared.global [%0], [%1], 16;" :: "r"(s), "l"(gmem));
}
__device__ __forceinline__ void cp_commit() {
    asm volatile("cp.async.commit_group;");
}
template <int N>
__device__ __forceinline__ void cp_wait() {
    asm volatile("cp.async.wait_group %0;" :: "n"(N));
}

// ---- no-return vector atomic add ----
__device__ __forceinline__ void red_add4(float* p, float x, float y, float z, float w) {
    asm volatile("red.global.add.v4.f32 [%0], {%1, %2, %3, %4};"
                 :: "l"(p), "f"(x), "f"(y), "f"(z), "f"(w) : "memory");
}

// ============================================================
// K1: key per-sample sum & sumsq partials. grid (16, 4) x 256.
// ============================================================
__global__ void k_keystats(const float* __restrict__ key) {
    int b = blockIdx.x, p = blockIdx.y, tid = threadIdx.x;
    const float4* src = (const float4*)(key + (size_t)b * Dn);
    float s = 0.f, q = 0.f;
    for (int i = p * 1568 + tid; i < (p + 1) * 1568; i += 256) {
        float4 v = src[i];
        s += v.x + v.y + v.z + v.w;
        q += v.x * v.x + v.y * v.y + v.z * v.z + v.w * v.w;
    }
    #pragma unroll
    for (int o = 16; o; o >>= 1) {
        s += __shfl_xor_sync(0xFFFFFFFFu, s, o);
        q += __shfl_xor_sync(0xFFFFFFFFu, q, o);
    }
    __shared__ float ss[8], sq[8];
    int w = tid >> 5;
    if ((tid & 31) == 0) { ss[w] = s; sq[w] = q; }
    __syncthreads();
    if (tid == 0) {
        float S = 0.f, Q = 0.f;
        #pragma unroll
        for (int i = 0; i < 8; ++i) { S += ss[i]; Q += sq[i]; }
        g_kps[b * 4 + p] = S;
        g_kpq[b * 4 + p] = Q;
    }
}

// =======================================================================
// K2: partial dots + partial sumsq. grid (125, 7) x 256 threads.
// Block owns 16 memory rows, 28 d-chunks of 128 floats (d-split by grid.y).
// Key chunk (16x128) and mem chunk (16x128) staged via 3-stage cp.async
// pipeline (2 chunks of DRAM latency hidden, zero register cost).
// Lane layout per warp: bit7=bh (which 8 b's), bits[6:5]=u_hi, bits[4:3]=g
// (which 4 n's), bits[2:0]=u_lo. d-lane = u_hi*8+u_lo (4 floats each).
// g in-warp -> key LDS is a 4-way in-warp broadcast.
// =======================================================================
__global__ __launch_bounds__(256, 2) void k_dots(const float* __restrict__ key,
                                                 const float* __restrict__ mem) {
    __shared__ __align__(16) float sstage[3][2][16 * CHUNK];  // 48 KB exactly
    // overlay: reduction scratch reuses stage memory AFTER the chunk loop
    float* sred = &sstage[0][0][0];   // 256 floats [bh][g][bb][r]
    float* ssq  = sred + 256;         // 16 floats  [g][r]

    int tid  = threadIdx.x;
    int bh   = tid >> 7;
    int g    = (tid >> 3) & 3;
    int u_lo = tid & 7;
    int dl   = ((tid >> 5) & 3) * 8 + u_lo;   // d-lane 0..31
    int nb   = blockIdx.x * 16;
    int sy   = blockIdx.y;
    int cbase = sy * CPB;

    unsigned long long acc[8][4];
    #pragma unroll
    for (int i = 0; i < 8; ++i)
        #pragma unroll
        for (int r = 0; r < 4; ++r) acc[i][r] = 0ull;
    unsigned long long sq2[4] = {0ull, 0ull, 0ull, 0ull};

    // staging lanes: thread copies one float4 of 2 key rows + 2 mem rows
    int row0 = tid >> 5;          // 0..7
    int j    = tid & 31;          // float4 within row

    const float* kr0 = key + (size_t)row0 * Dn + j * 4;
    const float* kr1 = key + (size_t)(row0 + 8) * Dn + j * 4;
    const float* mr0 = mem + (size_t)(nb + row0) * Dn + j * 4;
    const float* mr1 = mem + (size_t)(nb + row0 + 8) * Dn + j * 4;

    int so = row0 * CHUNK + j * 4;        // smem float offset (rows 0..7)
    int so8 = (row0 + 8) * CHUNK + j * 4; // smem float offset (rows 8..15)

    // prologue: stages 0 and 1
    #pragma unroll
    for (int s = 0; s < 2; ++s) {
        int off = (cbase + s) * CHUNK;
        cp16(&sstage[s][0][so],  kr0 + off);
        cp16(&sstage[s][0][so8], kr1 + off);
        cp16(&sstage[s][1][so],  mr0 + off);
        cp16(&sstage[s][1][so8], mr1 + off);
        cp_commit();
    }

    for (int cc = 0; cc < CPB; ++cc) {
        int buf = cc % 3;
        cp_wait<1>();          // stage cc landed (2+cc commits, <=1 pending)
        __syncthreads();       // visible to all; prev compute done

        if (cc + 2 < CPB) {    // issue stage cc+2 into buf (cc+2)%3
            int st  = (cc + 2) % 3;
            int off = (cbase + cc + 2) * CHUNK;
            cp16(&sstage[st][0][so],  kr0 + off);
            cp16(&sstage[st][0][so8], kr1 + off);
            cp16(&sstage[st][1][so],  mr0 + off);
            cp16(&sstage[st][1][so8], mr1 + off);
        }
        cp_commit();           // commit every iter to keep group accounting

        const float* km = &sstage[buf][0][0];
        const float* mm = &sstage[buf][1][0];
        ulonglong2 mv[4];
        #pragma unroll
        for (int r = 0; r < 4; ++r)
            mv[r] = *(const ulonglong2*)&mm[(g * 4 + r) * CHUNK + dl * 4];
        if (bh == 0) {
            #pragma unroll
            for (int r = 0; r < 4; ++r) {
                fma2(sq2[r], mv[r].x, mv[r].x);
                fma2(sq2[r], mv[r].y, mv[r].y);
            }
        }
        #pragma unroll
        for (int bb = 0; bb < 8; ++bb) {
            ulonglong2 kv = *(const ulonglong2*)&km[(bh * 8 + bb) * CHUNK + dl * 4];
            #pragma unroll
            for (int r = 0; r < 4; ++r) {
                fma2(acc[bb][r], kv.x, mv[r].x);
                fma2(acc[bb][r], kv.y, mv[r].y);
            }
        }
    }
    __syncthreads();
    // zero the overlaid reduction scratch
    sred[tid] = 0.f;          // covers sred[256]... tid 0..255
    if (tid < 16) ssq[tid] = 0.f;   // ssq overlaps sred? no: ssq = sred+256
    __syncthreads();

    // reduce: butterfly over u_lo (8 lanes), then smem-atomic across 4 u_hi warps
    #pragma unroll
    for (int bb = 0; bb < 8; ++bb)
        #pragma unroll
        for (int r = 0; r < 4; ++r) {
            float v = f2lo(acc[bb][r]) + f2hi(acc[bb][r]);
            v += __shfl_xor_sync(0xFFFFFFFFu, v, 1);
            v += __shfl_xor_sync(0xFFFFFFFFu, v, 2);
            v += __shfl_xor_sync(0xFFFFFFFFu, v, 4);
            if (bb == u_lo)
                atomicAdd(&sred[bh * 128 + g * 32 + bb * 4 + r], v);
        }
    if (bh == 0) {
        #pragma unroll
        for (int r = 0; r < 4; ++r) {
            float v = f2lo(sq2[r]) + f2hi(sq2[r]);
            v += __shfl_xor_sync(0xFFFFFFFFu, v, 1);
            v += __shfl_xor_sync(0xFFFFFFFFu, v, 2);
            v += __shfl_xor_sync(0xFFFFFFFFu, v, 4);
            if (u_lo == r) atomicAdd(&ssq[g * 4 + r], v);
        }
    }
    __syncthreads();

    {   // write 256 partial dots
        int r = tid & 3, bb = (tid >> 2) & 7, gg = (tid >> 5) & 3, b2 = tid >> 7;
        int b = b2 * 8 + bb, n = nb + gg * 4 + r;
        g_dotp[((size_t)sy * Bn + b) * Nn + n] = sred[b2 * 128 + gg * 32 + bb * 4 + r];
    }
    if (tid < 16) {
        int r = tid & 3, gg = tid >> 2;
        g_sqp[(size_t)sy * Nn + nb + gg * 4 + r] = ssq[gg * 4 + r];
    }
}

// ============================================================
// K3: sum partials -> cos -> tan -> softmax; write transposed
// duplicated weights (w,w). grid 16 x 256.
// ============================================================
__global__ void k_softmax() {
    int b = blockIdx.x, tid = threadIdx.x;
    __shared__ float sbuf[256];
    __shared__ float s_kfac;

    if (tid == 0) {
        float S = 0.f, Q = 0.f;
        #pragma unroll
        for (int p = 0; p < 4; ++p) { S += g_kps[b * 4 + p]; Q += g_kpq[b * 4 + p]; }
        S += 1e-7f;                                   // EPS_SUM
        // (s+eps)*kn = max(sqrt(sq_key), 1e-8*(s+eps))
        s_kfac = 1.f / fmaxf(sqrtf(Q), 1e-8f * S);
    }
    __syncthreads();
    float kf = s_kfac;

    float tv[8];
    float mx = -3.4e38f;
    #pragma unroll
    for (int i = 0; i < 8; ++i) {
        int n = tid + i * 256;
        if (n < Nn) {
            float dot = 0.f, sqv = 0.f;
            #pragma unroll
            for (int p = 0; p < DSPLIT; ++p) {
                dot += g_dotp[((size_t)p * Bn + b) * Nn + n];
                sqv += g_sqp[(size_t)p * Nn + n];
            }
            float mn = fmaxf(sqrtf(sqv), 1e-8f);
            float cosv = dot * kf / mn;
            float t = tanf(cosv * PI2F);
            tv[i] = t;
            mx = fmaxf(mx, t);
        } else tv[i] = -3.4e38f;
    }
    sbuf[tid] = mx; __syncthreads();
    for (int s = 128; s; s >>= 1) {
        if (tid < s) sbuf[tid] = fmaxf(sbuf[tid], sbuf[tid + s]);
        __syncthreads();
    }
    mx = sbuf[0];
    __syncthreads();

    float sum = 0.f;
    #pragma unroll
    for (int i = 0; i < 8; ++i) {
        int n = tid + i * 256;
        if (n < Nn) { float e = expf(tv[i] - mx); tv[i] = e; sum += e; }
    }
    sbuf[tid] = sum; __syncthreads();
    for (int s = 128; s; s >>= 1) {
        if (tid < s) sbuf[tid] += sbuf[tid + s];
        __syncthreads();
    }
    float inv = 1.f / sbuf[0];

    #pragma unroll
    for (int i = 0; i < 8; ++i) {
        int n = tid + i * 256;
        if (n < Nn) {
            float w = tv[i] * inv;
            g_w2[(size_t)n * Bn + b] = make_float2(w, w);  // pre-duplicated pair
        }
    }
}

// =======================================================================
// K4: out[b][d] = sum_n w[b][n] * mem[n][d]. grid (49, 12) x 128 threads.
// 588 blocks = exactly one occ-4 wave (592 slots on 148 SMs).
// Thread owns 4 consecutive d; 16 b accumulators as f32x2 pairs.
// Mem rows flow through a per-thread 8-stage cp.async pipeline (7 rows of
// DRAM latency in flight, no barriers). Weight tile staged in smem once.
// Partials combined via red.global.add.v4.f32 (no-return vector atomic).
// =======================================================================
__global__ __launch_bounds__(128, 4) void k_read(const float* __restrict__ mem,
                                                 float* __restrict__ out) {
    __shared__ __align__(16) ulonglong2 sw[167 * 8];     // 21376 B weight tile
    __shared__ __align__(16) char smrow[8][2048];        // 16 KB pipeline

    int tid = threadIdx.x;
    int d   = blockIdx.x * 512 + tid * 4;
    int y   = blockIdx.y;
    int n0  = (y < 8) ? y * 167 : 1336 + (y - 8) * 166;
    int cnt = (y < 8) ? 167 : 166;

    // stage weight tile: cnt x 128B
    {
        const float4* src = (const float4*)(g_w2 + (size_t)n0 * Bn);
        for (int i = tid; i < cnt * 8; i += 128)
            ((float4*)sw)[i] = src[i];
    }

    unsigned long long acc[16][2];
    #pragma unroll
    for (int b = 0; b < 16; ++b) { acc[b][0] = 0ull; acc[b][1] = 0ull; }

    const float* mp = mem + (size_t)n0 * Dn + d;
    // prologue: 7 rows in flight (cnt >= 166 always)
    #pragma unroll
    for (int s = 0; s < 7; ++s) {
        cp16(&smrow[s][tid * 16], mp + (size_t)s * Dn);
        cp_commit();
    }
    const float* pf = mp + (size_t)7 * Dn;
    __syncthreads();   // weight tile ready

    for (int n = 0; n < cnt; ++n) {
        cp_wait<6>();  // per-thread: stage n landed
        ulonglong2 cur = *(const ulonglong2*)&smrow[n & 7][tid * 16];
        if (n + 7 < cnt) cp16(&smrow[(n + 7) & 7][tid * 16], pf);
        cp_commit();
        pf += Dn;
        const ulonglong2* wq = sw + n * 8;
        #pragma unroll
        for (int q = 0; q < 8; ++q) {
            ulonglong2 wv = wq[q];                // (w2q,w2q),(w2q+1,w2q+1)
            fma2(acc[2 * q    ][0], wv.x, cur.x);
            fma2(acc[2 * q    ][1], wv.x, cur.y);
            fma2(acc[2 * q + 1][0], wv.y, cur.x);
            fma2(acc[2 * q + 1][1], wv.y, cur.y);
        }
    }

    #pragma unroll
    for (int b = 0; b < 16; ++b) {
        float* o = out + (size_t)b * Dn + d;
        red_add4(o, f2lo(acc[b][0]), f2hi(acc[b][0]),
                    f2lo(acc[b][1]), f2hi(acc[b][1]));
    }
}

// ============================================================
extern "C" void kernel_launch(void* const* d_in, const int* in_sizes, int n_in,
                              void* d_out, int out_size) {
    const float* key = (const float*)d_in[0];
    const float* mem = (const float*)d_in[1];
    // metadata order is key, memory; swap defensively if sizes say otherwise
    if (n_in >= 2 && in_sizes[0] == Nn * Dn) {
        key = (const float*)d_in[1];
        mem = (const float*)d_in[0];
    }
    float* out = (float*)d_out;

    cudaMemsetAsync(d_out, 0, (size_t)out_size * sizeof(float), 0);
    k_keystats<<<dim3(16, 4), 256>>>(key);
    k_dots<<<dim3(125, DSPLIT), 256>>>(key, mem);
    k_softmax<<<16, 256>>>();
    k_read<<<dim3(49, 12), 128>>>(mem, out);
}

// round 11
// speedup vs baseline: 2.3752x; 1.0178x over previous
#include <cuda_runtime.h>
#include <cuda_bf16.h>
#include <math.h>

// Problem constants (fixed shapes): B=16, N=2000, C=512, H=W=7
#define Bn 16
#define Nn 2000
#define Dn 25088            // 512*7*7
#define PI2F ((float)(3.14159 / 2.0))   // matches reference constant exactly
#define CHUNK 128           // floats per d-chunk in k_dots
#define DSPLIT 7            // d-split for k_dots
#define CPB 28              // chunks per block = (25088/128)/7
#define KSTG 5              // k_dots pipeline stages
#define RSTG 12             // k_read pipeline stages

// ---- device scratch (static allocation only; no cudaMalloc allowed) ----
__device__ float  g_dotp[DSPLIT * Bn * Nn];  // partial dots per d-split, [p][b][n]
__device__ float  g_sqp[DSPLIT * Nn];        // partial row sumsq per d-split, [p][n]
__device__ float  g_kps[Bn * DSPLIT];        // key sum partials, [b][sy]
__device__ float  g_kpq[Bn * DSPLIT];        // key sumsq partials, [b][sy]
__device__ __align__(16) float2 g_w2[Nn * Bn];  // weights, [n][b], duplicated (w,w)

// ---- packed fp32x2 FMA (sm_100+; ptxas will not auto-generate this) ----
__device__ __forceinline__ void fma2(unsigned long long& acc,
                                     unsigned long long a,
                                     unsigned long long b) {
    asm("fma.rn.f32x2 %0, %1, %2, %0;" : "+l"(acc) : "l"(a), "l"(b));
}
__device__ __forceinline__ float f2lo(unsigned long long v) {
    return __uint_as_float((unsigned)(v & 0xFFFFFFFFull));
}
__device__ __forceinline__ float f2hi(unsigned long long v) {
    return __uint_as_float((unsigned)(v >> 32));
}

// ---- cp.async (LDGSTS) helpers ----
__device__ __forceinline__ void cp16(void* smem, const void* gmem) {
    unsigned s = (unsigned)__cvta_generic_to_shared(smem);
    asm volatile("cp.async.cg.shared.global [%0], [%1], 16;" :: "r"(s), "l"(gmem));
}
__device__ __forceinline__ void cp_commit() {
    asm volatile("cp.async.commit_group;");
}
template <int N>
__device__ __forceinline__ void cp_wait() {
    asm volatile("cp.async.wait_group %0;" :: "n"(N));
}

// ---- no-return vector atomic add ----
__device__ __forceinline__ void red_add4(float* p, float x, float y, float z, float w) {
    asm volatile("red.global.add.v4.f32 [%0], {%1, %2, %3, %4};"
                 :: "l"(p), "f"(x), "f"(y), "f"(z), "f"(w) : "memory");
}

// =======================================================================
// K2: partial dots + partial sumsq (+ fused key stats in x==0 blocks).
// grid (125, 7) x 256 threads. Block owns 16 memory rows, 28 d-chunks of
// 128 floats (d-split by grid.y). Key chunk (16x128) and mem chunk (16x128)
// staged via 5-stage cp.async pipeline (~3.5 chunks of latency in flight).
// Dynamic smem: 5 stages x (key 8KB + mem 8KB) = 80KB.
// Lane layout per warp: bit7=bh (which 8 b's), bits[6:5]=u_hi, bits[4:3]=g
// (which 4 n's), bits[2:0]=u_lo. d-lane = u_hi*8+u_lo (4 floats each).
// g in-warp -> key LDS is a 4-way in-warp broadcast.
// =======================================================================
__global__ __launch_bounds__(256, 2) void k_dots(const float* __restrict__ key,
                                                 const float* __restrict__ mem) {
    extern __shared__ __align__(16) float sdyn[];   // KSTG * 4096 floats
    // overlay after the chunk loop: reduction scratch on stage 0
    float* sred = sdyn;          // 256 floats [bh][g][bb][r]
    float* ssq  = sdyn + 256;    // 16 floats  [g][r]

    int tid  = threadIdx.x;
    int bh   = tid >> 7;
    int g    = (tid >> 3) & 3;
    int u_lo = tid & 7;
    int dl   = ((tid >> 5) & 3) * 8 + u_lo;   // d-lane 0..31
    int nb   = blockIdx.x * 16;
    int sy   = blockIdx.y;
    int cbase = sy * CPB;
    bool bx0 = (blockIdx.x == 0);

    unsigned long long acc[8][4];
    #pragma unroll
    for (int i = 0; i < 8; ++i)
        #pragma unroll
        for (int r = 0; r < 4; ++r) acc[i][r] = 0ull;
    unsigned long long sq2[4] = {0ull, 0ull, 0ull, 0ull};
    float ks = 0.f, kq = 0.f;    // fused key stats (x==0 blocks only)

    // staging lanes: thread copies one float4 of 2 key rows + 2 mem rows
    int row0 = tid >> 5;          // 0..7
    int j    = tid & 31;          // float4 within row

    const float* kr0 = key + (size_t)row0 * Dn + j * 4;
    const float* kr1 = key + (size_t)(row0 + 8) * Dn + j * 4;
    const float* mr0 = mem + (size_t)(nb + row0) * Dn + j * 4;
    const float* mr1 = mem + (size_t)(nb + row0 + 8) * Dn + j * 4;

    int so  = row0 * CHUNK + j * 4;        // smem float offset (rows 0..7)
    int so8 = (row0 + 8) * CHUNK + j * 4;  // smem float offset (rows 8..15)

    // prologue: stages 0..3 in flight
    #pragma unroll
    for (int s = 0; s < KSTG - 1; ++s) {
        float* st = sdyn + s * 4096;
        int off = (cbase + s) * CHUNK;
        cp16(st + so,         kr0 + off);
        cp16(st + so8,        kr1 + off);
        cp16(st + 2048 + so,  mr0 + off);
        cp16(st + 2048 + so8, mr1 + off);
        cp_commit();
    }

    int bufc = 0, bufi = KSTG - 1;
    for (int cc = 0; cc < CPB; ++cc) {
        cp_wait<KSTG - 2>();   // stage cc landed
        __syncthreads();       // visible to all; prior compute on bufi done

        if (cc + KSTG - 1 < CPB) {   // issue stage cc+4 into bufi
            float* st = sdyn + bufi * 4096;
            int off = (cbase + cc + KSTG - 1) * CHUNK;
            cp16(st + so,         kr0 + off);
            cp16(st + so8,        kr1 + off);
            cp16(st + 2048 + so,  mr0 + off);
            cp16(st + 2048 + so8, mr1 + off);
        }
        cp_commit();           // commit every iter to keep group accounting
        if (++bufi == KSTG) bufi = 0;

        const float* km = sdyn + bufc * 4096;
        const float* mm = km + 2048;
        if (++bufc == KSTG) bufc = 0;

        ulonglong2 mv[4];
        #pragma unroll
        for (int r = 0; r < 4; ++r)
            mv[r] = *(const ulonglong2*)&mm[(g * 4 + r) * CHUNK + dl * 4];
        if (bh == 0) {
            #pragma unroll
            for (int r = 0; r < 4; ++r) {
                fma2(sq2[r], mv[r].x, mv[r].x);
                fma2(sq2[r], mv[r].y, mv[r].y);
            }
        }
        #pragma unroll
        for (int bb = 0; bb < 8; ++bb) {
            ulonglong2 kv = *(const ulonglong2*)&km[(bh * 8 + bb) * CHUNK + dl * 4];
            #pragma unroll
            for (int r = 0; r < 4; ++r) {
                fma2(acc[bb][r], kv.x, mv[r].x);
                fma2(acc[bb][r], kv.y, mv[r].y);
            }
        }

        if (bx0) {   // fused key stats: thread covers b=tid>>4, 8 floats of d
            const float* kc = km + (tid >> 4) * CHUNK + (tid & 15) * 8;
            float4 v0 = *(const float4*)kc;
            float4 v1 = *(const float4*)(kc + 4);
            ks += (v0.x + v0.y) + (v0.z + v0.w) + (v1.x + v1.y) + (v1.z + v1.w);
            kq = fmaf(v0.x, v0.x, kq); kq = fmaf(v0.y, v0.y, kq);
            kq = fmaf(v0.z, v0.z, kq); kq = fmaf(v0.w, v0.w, kq);
            kq = fmaf(v1.x, v1.x, kq); kq = fmaf(v1.y, v1.y, kq);
            kq = fmaf(v1.z, v1.z, kq); kq = fmaf(v1.w, v1.w, kq);
        }
    }
    __syncthreads();   // all cp groups drained by last wait; safe to overlay
    sred[tid] = 0.f;   // zero overlaid reduction scratch (sred[256] + ssq[16])
    if (tid < 16) ssq[tid] = 0.f;
    __syncthreads();

    // key-stat reduce within 16-lane half-warps (same b), write per-sy partial
    if (bx0) {
        #pragma unroll
        for (int o = 1; o < 16; o <<= 1) {
            ks += __shfl_xor_sync(0xFFFFFFFFu, ks, o);
            kq += __shfl_xor_sync(0xFFFFFFFFu, kq, o);
        }
        if ((tid & 15) == 0) {
            g_kps[(tid >> 4) * DSPLIT + sy] = ks;
            g_kpq[(tid >> 4) * DSPLIT + sy] = kq;
        }
    }

    // reduce: butterfly over u_lo (8 lanes), then smem-atomic across 4 u_hi warps
    #pragma unroll
    for (int bb = 0; bb < 8; ++bb)
        #pragma unroll
        for (int r = 0; r < 4; ++r) {
            float v = f2lo(acc[bb][r]) + f2hi(acc[bb][r]);
            v += __shfl_xor_sync(0xFFFFFFFFu, v, 1);
            v += __shfl_xor_sync(0xFFFFFFFFu, v, 2);
            v += __shfl_xor_sync(0xFFFFFFFFu, v, 4);
            if (bb == u_lo)
                atomicAdd(&sred[bh * 128 + g * 32 + bb * 4 + r], v);
        }
    if (bh == 0) {
        #pragma unroll
        for (int r = 0; r < 4; ++r) {
            float v = f2lo(sq2[r]) + f2hi(sq2[r]);
            v += __shfl_xor_sync(0xFFFFFFFFu, v, 1);
            v += __shfl_xor_sync(0xFFFFFFFFu, v, 2);
            v += __shfl_xor_sync(0xFFFFFFFFu, v, 4);
            if (u_lo == r) atomicAdd(&ssq[g * 4 + r], v);
        }
    }
    __syncthreads();

    {   // write 256 partial dots
        int r = tid & 3, bb = (tid >> 2) & 7, gg = (tid >> 5) & 3, b2 = tid >> 7;
        int b = b2 * 8 + bb, n = nb + gg * 4 + r;
        g_dotp[((size_t)sy * Bn + b) * Nn + n] = sred[b2 * 128 + gg * 32 + bb * 4 + r];
    }
    if (tid < 16) {
        int r = tid & 3, gg = tid >> 2;
        g_sqp[(size_t)sy * Nn + nb + gg * 4 + r] = ssq[gg * 4 + r];
    }
}

// ============================================================
// K3: sum partials -> cos -> tan -> softmax; write transposed
// duplicated weights (w,w). grid 16 x 256.
// ============================================================
__global__ void k_softmax() {
    int b = blockIdx.x, tid = threadIdx.x;
    __shared__ float sbuf[256];
    __shared__ float s_kfac;

    if (tid == 0) {
        float S = 0.f, Q = 0.f;
        #pragma unroll
        for (int p = 0; p < DSPLIT; ++p) {
            S += g_kps[b * DSPLIT + p];
            Q += g_kpq[b * DSPLIT + p];
        }
        S += 1e-7f;                                   // EPS_SUM
        // (s+eps)*kn = max(sqrt(sq_key), 1e-8*(s+eps))
        s_kfac = 1.f / fmaxf(sqrtf(Q), 1e-8f * S);
    }
    __syncthreads();
    float kf = s_kfac;

    float tv[8];
    float mx = -3.4e38f;
    #pragma unroll
    for (int i = 0; i < 8; ++i) {
        int n = tid + i * 256;
        if (n < Nn) {
            float dot = 0.f, sqv = 0.f;
            #pragma unroll
            for (int p = 0; p < DSPLIT; ++p) {
                dot += g_dotp[((size_t)p * Bn + b) * Nn + n];
                sqv += g_sqp[(size_t)p * Nn + n];
            }
            float mn = fmaxf(sqrtf(sqv), 1e-8f);
            float cosv = dot * kf / mn;
            float t = tanf(cosv * PI2F);
            tv[i] = t;
            mx = fmaxf(mx, t);
        } else tv[i] = -3.4e38f;
    }
    sbuf[tid] = mx; __syncthreads();
    for (int s = 128; s; s >>= 1) {
        if (tid < s) sbuf[tid] = fmaxf(sbuf[tid], sbuf[tid + s]);
        __syncthreads();
    }
    mx = sbuf[0];
    __syncthreads();

    float sum = 0.f;
    #pragma unroll
    for (int i = 0; i < 8; ++i) {
        int n = tid + i * 256;
        if (n < Nn) { float e = expf(tv[i] - mx); tv[i] = e; sum += e; }
    }
    sbuf[tid] = sum; __syncthreads();
    for (int s = 128; s; s >>= 1) {
        if (tid < s) sbuf[tid] += sbuf[tid + s];
        __syncthreads();
    }
    float inv = 1.f / sbuf[0];

    #pragma unroll
    for (int i = 0; i < 8; ++i) {
        int n = tid + i * 256;
        if (n < Nn) {
            float w = tv[i] * inv;
            g_w2[(size_t)n * Bn + b] = make_float2(w, w);  // pre-duplicated pair
        }
    }
}

// =======================================================================
// K4: out[b][d] = sum_n w[b][n] * mem[n][d]. grid (49, 12) x 128 threads.
// 588 blocks = exactly one occ-4 wave (592 slots on 148 SMs).
// Thread owns 4 consecutive d; 16 b accumulators as f32x2 pairs.
// Mem rows flow through a per-thread 12-stage cp.async pipeline (11 rows of
// DRAM latency in flight, no barriers). Weight tile staged in smem once.
// Partials combined via red.global.add.v4.f32 (no-return vector atomic).
// =======================================================================
__global__ __launch_bounds__(128, 4) void k_read(const float* __restrict__ mem,
                                                 float* __restrict__ out) {
    __shared__ __align__(16) ulonglong2 sw[167 * 8];     // 21376 B weight tile
    __shared__ __align__(16) char smrow[RSTG][2048];     // 24 KB pipeline

    int tid = threadIdx.x;
    int d   = blockIdx.x * 512 + tid * 4;
    int y   = blockIdx.y;
    int n0  = (y < 8) ? y * 167 : 1336 + (y - 8) * 166;
    int cnt = (y < 8) ? 167 : 166;

    // stage weight tile: cnt x 128B
    {
        const float4* src = (const float4*)(g_w2 + (size_t)n0 * Bn);
        for (int i = tid; i < cnt * 8; i += 128)
            ((float4*)sw)[i] = src[i];
    }

    unsigned long long acc[16][2];
    #pragma unroll
    for (int b = 0; b < 16; ++b) { acc[b][0] = 0ull; acc[b][1] = 0ull; }

    const float* mp = mem + (size_t)n0 * Dn + d;
    // prologue: 11 rows in flight (cnt >= 166 always)
    #pragma unroll
    for (int s = 0; s < RSTG - 1; ++s) {
        cp16(&smrow[s][tid * 16], mp + (size_t)s * Dn);
        cp_commit();
    }
    const float* pf = mp + (size_t)(RSTG - 1) * Dn;
    __syncthreads();   // weight tile ready

    int slc = 0, sli = RSTG - 1;
    for (int n = 0; n < cnt; ++n) {
        cp_wait<RSTG - 2>();  // per-thread: stage n landed
        ulonglong2 cur = *(const ulonglong2*)&smrow[slc][tid * 16];
        if (++slc == RSTG) slc = 0;
        if (n + RSTG - 1 < cnt) cp16(&smrow[sli][tid * 16], pf);
        cp_commit();
        if (++sli == RSTG) sli = 0;
        pf += Dn;
        const ulonglong2* wq = sw + n * 8;
        #pragma unroll
        for (int q = 0; q < 8; ++q) {
            ulonglong2 wv = wq[q];                // (w2q,w2q),(w2q+1,w2q+1)
            fma2(acc[2 * q    ][0], wv.x, cur.x);
            fma2(acc[2 * q    ][1], wv.x, cur.y);
            fma2(acc[2 * q + 1][0], wv.y, cur.x);
            fma2(acc[2 * q + 1][1], wv.y, cur.y);
        }
    }

    #pragma unroll
    for (int b = 0; b < 16; ++b) {
        float* o = out + (size_t)b * Dn + d;
        red_add4(o, f2lo(acc[b][0]), f2hi(acc[b][0]),
                    f2lo(acc[b][1]), f2hi(acc[b][1]));
    }
}

// ============================================================
extern "C" void kernel_launch(void* const* d_in, const int* in_sizes, int n_in,
                              void* d_out, int out_size) {
    const float* key = (const float*)d_in[0];
    const float* mem = (const float*)d_in[1];
    // metadata order is key, memory; swap defensively if sizes say otherwise
    if (n_in >= 2 && in_sizes[0] == Nn * Dn) {
        key = (const float*)d_in[1];
        mem = (const float*)d_in[0];
    }
    float* out = (float*)d_out;

    // 80KB dynamic smem for k_dots (attribute persists from the harness's
    // non-captured correctness call, so capture-time behavior is identical)
    const int kdots_smem = KSTG * 4096 * (int)sizeof(float);
    cudaFuncSetAttribute(k_dots, cudaFuncAttributeMaxDynamicSharedMemorySize,
                         kdots_smem);

    cudaMemsetAsync(d_out, 0, (size_t)out_size * sizeof(float), 0);
    k_dots<<<dim3(125, DSPLIT), 256, kdots_smem>>>(key, mem);
    k_softmax<<<16, 256>>>();
    k_read<<<dim3(49, 12), 128>>>(mem, out);
}

// round 12
// speedup vs baseline: 2.3829x; 1.0032x over previous
#include <cuda_runtime.h>
#include <cuda_bf16.h>
#include <math.h>

// Problem constants (fixed shapes): B=16, N=2000, C=512, H=W=7
#define Bn 16
#define Nn 2000
#define Dn 25088            // 512*7*7
#define PI2F ((float)(3.14159 / 2.0))   // matches reference constant exactly
#define CHUNK 128           // floats per d-chunk in k_dots
#define DSPLIT 7            // d-split for k_dots
#define CPB 28              // chunks per block = (25088/128)/7
#define KSTG 4              // k_dots pipeline stages (ring unrolled away)
#define RSTG 12             // k_read pipeline stages

// ---- device scratch (static allocation only; no cudaMalloc allowed) ----
__device__ float  g_dotp[DSPLIT * Bn * Nn];  // partial dots per d-split, [p][b][n]
__device__ float  g_sqp[DSPLIT * Nn];        // partial row sumsq per d-split, [p][n]
__device__ float  g_kps[Bn * DSPLIT];        // key sum partials, [b][sy]
__device__ float  g_kpq[Bn * DSPLIT];        // key sumsq partials, [b][sy]
__device__ __align__(16) float2 g_w2[Nn * Bn];  // weights, [n][b], duplicated (w,w)

// ---- packed fp32x2 FMA (sm_100+; ptxas will not auto-generate this) ----
__device__ __forceinline__ void fma2(unsigned long long& acc,
                                     unsigned long long a,
                                     unsigned long long b) {
    asm("fma.rn.f32x2 %0, %1, %2, %0;" : "+l"(acc) : "l"(a), "l"(b));
}
__device__ __forceinline__ float f2lo(unsigned long long v) {
    return __uint_as_float((unsigned)(v & 0xFFFFFFFFull));
}
__device__ __forceinline__ float f2hi(unsigned long long v) {
    return __uint_as_float((unsigned)(v >> 32));
}

// ---- cp.async (LDGSTS) helpers ----
__device__ __forceinline__ void cp16(void* smem, const void* gmem) {
    unsigned s = (unsigned)__cvta_generic_to_shared(smem);
    asm volatile("cp.async.cg.shared.global [%0], [%1], 16;" :: "r"(s), "l"(gmem));
}
__device__ __forceinline__ void cp_commit() {
    asm volatile("cp.async.commit_group;");
}
template <int N>
__device__ __forceinline__ void cp_wait() {
    asm volatile("cp.async.wait_group %0;" :: "n"(N));
}

// ---- no-return vector atomic add ----
__device__ __forceinline__ void red_add4(float* p, float x, float y, float z, float w) {
    asm volatile("red.global.add.v4.f32 [%0], {%1, %2, %3, %4};"
                 :: "l"(p), "f"(x), "f"(y), "f"(z), "f"(w) : "memory");
}

// =======================================================================
// K2: partial dots + partial sumsq (+ fused key stats in x==0 blocks).
// grid (125, 7) x 256 threads. Block owns 16 memory rows, 28 d-chunks of
// 128 floats (d-split by grid.y). Key chunk (16x128) and mem chunk (16x128)
// staged via 4-stage cp.async pipeline; the chunk loop is unrolled 4-wide
// (CPB = 7*4) so ALL stage bases / smem addresses are compile-time constant
// and global staging pointers are pure induction variables.
// Dynamic smem: 4 stages x (key 8KB + mem 8KB) = 64KB.
// Lane layout per warp: bit7=bh (which 8 b's), bits[6:5]=u_hi, bits[4:3]=g
// (which 4 n's), bits[2:0]=u_lo. d-lane = u_hi*8+u_lo (4 floats each).
// g in-warp -> key LDS is a 4-way in-warp broadcast.
// =======================================================================
__global__ __launch_bounds__(256, 2) void k_dots(const float* __restrict__ key,
                                                 const float* __restrict__ mem) {
    extern __shared__ __align__(16) float sdyn[];   // KSTG * 4096 floats
    // overlay after the chunk loop: reduction scratch on stage 0
    float* sred = sdyn;          // 256 floats [bh][g][bb][r]
    float* ssq  = sdyn + 256;    // 16 floats  [g][r]

    int tid  = threadIdx.x;
    int bh   = tid >> 7;
    int g    = (tid >> 3) & 3;
    int u_lo = tid & 7;
    int dl   = ((tid >> 5) & 3) * 8 + u_lo;   // d-lane 0..31
    int nb   = blockIdx.x * 16;
    int sy   = blockIdx.y;
    int cbase = sy * CPB;
    bool bx0 = (blockIdx.x == 0);

    unsigned long long acc[8][4];
    #pragma unroll
    for (int i = 0; i < 8; ++i)
        #pragma unroll
        for (int r = 0; r < 4; ++r) acc[i][r] = 0ull;
    unsigned long long sq2[4] = {0ull, 0ull, 0ull, 0ull};
    float ks = 0.f, kq = 0.f;    // fused key stats (x==0 blocks only)

    // staging lanes: thread copies one float4 of 2 key rows + 2 mem rows
    int row0 = tid >> 5;          // 0..7
    int j    = tid & 31;          // float4 within row

    // induction-variable global pointers (advance by 4*CHUNK per tt)
    const float* pk0 = key + (size_t)row0 * Dn + j * 4 + cbase * CHUNK;
    const float* pk1 = key + (size_t)(row0 + 8) * Dn + j * 4 + cbase * CHUNK;
    const float* pm0 = mem + (size_t)(nb + row0) * Dn + j * 4 + cbase * CHUNK;
    const float* pm1 = mem + (size_t)(nb + row0 + 8) * Dn + j * 4 + cbase * CHUNK;

    int so  = row0 * CHUNK + j * 4;        // smem float offset (rows 0..7)
    int so8 = (row0 + 8) * CHUNK + j * 4;  // smem float offset (rows 8..15)

    // per-thread constant compute offsets
    int mvoff = g * 4 * CHUNK + dl * 4;    // + r*CHUNK (const) inside
    int kvoff = bh * 8 * CHUNK + dl * 4;   // + bb*CHUNK (const) inside
    int ksoff = (tid >> 4) * CHUNK + (tid & 15) * 8;

    // prologue: stages 0..2 in flight
    #pragma unroll
    for (int s = 0; s < KSTG - 1; ++s) {
        float* st = sdyn + s * 4096;
        cp16(st + so,         pk0 + s * CHUNK);
        cp16(st + so8,        pk1 + s * CHUNK);
        cp16(st + 2048 + so,  pm0 + s * CHUNK);
        cp16(st + 2048 + so8, pm1 + s * CHUNK);
        cp_commit();
    }

    #pragma unroll 1
    for (int tt = 0; tt < 7; ++tt) {
        #pragma unroll
        for (int s = 0; s < 4; ++s) {
            const int c = tt * 4 + s;          // chunk index (s makes consts)
            cp_wait<KSTG - 2>();               // stage c landed
            __syncthreads();                   // visible; fill-target drained

            if (c + KSTG - 1 < CPB) {          // issue stage c+3
                float* st = sdyn + ((s + KSTG - 1) & 3) * 4096;
                const int go = (s + KSTG - 1) * CHUNK;   // + tt*4*CHUNK via ptr
                cp16(st + so,         pk0 + go);
                cp16(st + so8,        pk1 + go);
                cp16(st + 2048 + so,  pm0 + go);
                cp16(st + 2048 + so8, pm1 + go);
            }
            cp_commit();                       // unconditional: keeps accounting

            const float* km = sdyn + s * 4096; // compile-time stage base
            const float* mm = km + 2048;

            ulonglong2 mv[4];
            #pragma unroll
            for (int r = 0; r < 4; ++r)
                mv[r] = *(const ulonglong2*)&mm[mvoff + r * CHUNK];
            if (bh == 0) {
                #pragma unroll
                for (int r = 0; r < 4; ++r) {
                    fma2(sq2[r], mv[r].x, mv[r].x);
                    fma2(sq2[r], mv[r].y, mv[r].y);
                }
            }
            #pragma unroll
            for (int bb = 0; bb < 8; ++bb) {
                ulonglong2 kv = *(const ulonglong2*)&km[kvoff + bb * CHUNK];
                #pragma unroll
                for (int r = 0; r < 4; ++r) {
                    fma2(acc[bb][r], kv.x, mv[r].x);
                    fma2(acc[bb][r], kv.y, mv[r].y);
                }
            }

            if (bx0) {   // fused key stats: thread covers b=tid>>4, 8 d-floats
                const float* kc = km + ksoff;
                float4 v0 = *(const float4*)kc;
                float4 v1 = *(const float4*)(kc + 4);
                ks += (v0.x + v0.y) + (v0.z + v0.w) + (v1.x + v1.y) + (v1.z + v1.w);
                kq = fmaf(v0.x, v0.x, kq); kq = fmaf(v0.y, v0.y, kq);
                kq = fmaf(v0.z, v0.z, kq); kq = fmaf(v0.w, v0.w, kq);
                kq = fmaf(v1.x, v1.x, kq); kq = fmaf(v1.y, v1.y, kq);
                kq = fmaf(v1.z, v1.z, kq); kq = fmaf(v1.w, v1.w, kq);
            }
        }
        pk0 += 4 * CHUNK; pk1 += 4 * CHUNK;
        pm0 += 4 * CHUNK; pm1 += 4 * CHUNK;
    }
    __syncthreads();   // all cp groups drained; safe to overlay stage 0
    sred[tid] = 0.f;   // zero overlaid reduction scratch (sred[256] + ssq[16])
    if (tid < 16) ssq[tid] = 0.f;
    __syncthreads();

    // key-stat reduce within 16-lane half-warps (same b), write per-sy partial
    if (bx0) {
        #pragma unroll
        for (int o = 1; o < 16; o <<= 1) {
            ks += __shfl_xor_sync(0xFFFFFFFFu, ks, o);
            kq += __shfl_xor_sync(0xFFFFFFFFu, kq, o);
        }
        if ((tid & 15) == 0) {
            g_kps[(tid >> 4) * DSPLIT + sy] = ks;
            g_kpq[(tid >> 4) * DSPLIT + sy] = kq;
        }
    }

    // reduce: butterfly over u_lo (8 lanes), then smem-atomic across 4 u_hi warps
    #pragma unroll
    for (int bb = 0; bb < 8; ++bb)
        #pragma unroll
        for (int r = 0; r < 4; ++r) {
            float v = f2lo(acc[bb][r]) + f2hi(acc[bb][r]);
            v += __shfl_xor_sync(0xFFFFFFFFu, v, 1);
            v += __shfl_xor_sync(0xFFFFFFFFu, v, 2);
            v += __shfl_xor_sync(0xFFFFFFFFu, v, 4);
            if (bb == u_lo)
                atomicAdd(&sred[bh * 128 + g * 32 + bb * 4 + r], v);
        }
    if (bh == 0) {
        #pragma unroll
        for (int r = 0; r < 4; ++r) {
            float v = f2lo(sq2[r]) + f2hi(sq2[r]);
            v += __shfl_xor_sync(0xFFFFFFFFu, v, 1);
            v += __shfl_xor_sync(0xFFFFFFFFu, v, 2);
            v += __shfl_xor_sync(0xFFFFFFFFu, v, 4);
            if (u_lo == r) atomicAdd(&ssq[g * 4 + r], v);
        }
    }
    __syncthreads();

    {   // write 256 partial dots
        int r = tid & 3, bb = (tid >> 2) & 7, gg = (tid >> 5) & 3, b2 = tid >> 7;
        int b = b2 * 8 + bb, n = nb + gg * 4 + r;
        g_dotp[((size_t)sy * Bn + b) * Nn + n] = sred[b2 * 128 + gg * 32 + bb * 4 + r];
    }
    if (tid < 16) {
        int r = tid & 3, gg = tid >> 2;
        g_sqp[(size_t)sy * Nn + nb + gg * 4 + r] = ssq[gg * 4 + r];
    }
}

// ============================================================
// K3: sum partials -> cos -> tan -> softmax; write transposed
// duplicated weights (w,w). Also zeroes d_out (replaces memset;
// runs before k_read in-stream). grid 16 x 256.
// ============================================================
__global__ void k_softmax(float* __restrict__ out) {
    int b = blockIdx.x, tid = threadIdx.x;
    __shared__ float sbuf[256];
    __shared__ float s_kfac;

    // zero this block's slice of the output (Bn*Dn floats over 16 blocks)
    {
        float4 z = make_float4(0.f, 0.f, 0.f, 0.f);
        float4* o4 = (float4*)(out + (size_t)b * Dn);
        for (int i = tid; i < Dn / 4; i += 256) o4[i] = z;
    }

    if (tid == 0) {
        float S = 0.f, Q = 0.f;
        #pragma unroll
        for (int p = 0; p < DSPLIT; ++p) {
            S += g_kps[b * DSPLIT + p];
            Q += g_kpq[b * DSPLIT + p];
        }
        S += 1e-7f;                                   // EPS_SUM
        // (s+eps)*kn = max(sqrt(sq_key), 1e-8*(s+eps))
        s_kfac = 1.f / fmaxf(sqrtf(Q), 1e-8f * S);
    }
    __syncthreads();
    float kf = s_kfac;

    float tv[8];
    float mx = -3.4e38f;
    #pragma unroll
    for (int i = 0; i < 8; ++i) {
        int n = tid + i * 256;
        if (n < Nn) {
            float dot = 0.f, sqv = 0.f;
            #pragma unroll
            for (int p = 0; p < DSPLIT; ++p) {
                dot += g_dotp[((size_t)p * Bn + b) * Nn + n];
                sqv += g_sqp[(size_t)p * Nn + n];
            }
            float mn = fmaxf(sqrtf(sqv), 1e-8f);
            float cosv = dot * kf / mn;
            float t = tanf(cosv * PI2F);
            tv[i] = t;
            mx = fmaxf(mx, t);
        } else tv[i] = -3.4e38f;
    }
    sbuf[tid] = mx; __syncthreads();
    for (int s = 128; s; s >>= 1) {
        if (tid < s) sbuf[tid] = fmaxf(sbuf[tid], sbuf[tid + s]);
        __syncthreads();
    }
    mx = sbuf[0];
    __syncthreads();

    float sum = 0.f;
    #pragma unroll
    for (int i = 0; i < 8; ++i) {
        int n = tid + i * 256;
        if (n < Nn) { float e = expf(tv[i] - mx); tv[i] = e; sum += e; }
    }
    sbuf[tid] = sum; __syncthreads();
    for (int s = 128; s; s >>= 1) {
        if (tid < s) sbuf[tid] += sbuf[tid + s];
        __syncthreads();
    }
    float inv = 1.f / sbuf[0];

    #pragma unroll
    for (int i = 0; i < 8; ++i) {
        int n = tid + i * 256;
        if (n < Nn) {
            float w = tv[i] * inv;
            g_w2[(size_t)n * Bn + b] = make_float2(w, w);  // pre-duplicated pair
        }
    }
}

// =======================================================================
// K4: out[b][d] = sum_n w[b][n] * mem[n][d]. grid (49, 12) x 128 threads.
// 588 blocks = exactly one occ-4 wave (592 slots on 148 SMs).
// Thread owns 4 consecutive d; 16 b accumulators as f32x2 pairs.
// Mem rows flow through a per-thread 12-stage cp.async pipeline (11 rows of
// DRAM latency in flight, no barriers). Weight tile staged in smem once.
// Partials combined via red.global.add.v4.f32 (no-return vector atomic).
// =======================================================================
__global__ __launch_bounds__(128, 4) void k_read(const float* __restrict__ mem,
                                                 float* __restrict__ out) {
    __shared__ __align__(16) ulonglong2 sw[167 * 8];     // 21376 B weight tile
    __shared__ __align__(16) char smrow[RSTG][2048];     // 24 KB pipeline

    int tid = threadIdx.x;
    int d   = blockIdx.x * 512 + tid * 4;
    int y   = blockIdx.y;
    int n0  = (y < 8) ? y * 167 : 1336 + (y - 8) * 166;
    int cnt = (y < 8) ? 167 : 166;

    // stage weight tile: cnt x 128B
    {
        const float4* src = (const float4*)(g_w2 + (size_t)n0 * Bn);
        for (int i = tid; i < cnt * 8; i += 128)
            ((float4*)sw)[i] = src[i];
    }

    unsigned long long acc[16][2];
    #pragma unroll
    for (int b = 0; b < 16; ++b) { acc[b][0] = 0ull; acc[b][1] = 0ull; }

    const float* mp = mem + (size_t)n0 * Dn + d;
    // prologue: 11 rows in flight (cnt >= 166 always)
    #pragma unroll
    for (int s = 0; s < RSTG - 1; ++s) {
        cp16(&smrow[s][tid * 16], mp + (size_t)s * Dn);
        cp_commit();
    }
    const float* pf = mp + (size_t)(RSTG - 1) * Dn;
    __syncthreads();   // weight tile ready

    int slc = 0, sli = RSTG - 1;
    for (int n = 0; n < cnt; ++n) {
        cp_wait<RSTG - 2>();  // per-thread: stage n landed
        ulonglong2 cur = *(const ulonglong2*)&smrow[slc][tid * 16];
        if (++slc == RSTG) slc = 0;
        if (n + RSTG - 1 < cnt) cp16(&smrow[sli][tid * 16], pf);
        cp_commit();
        if (++sli == RSTG) sli = 0;
        pf += Dn;
        const ulonglong2* wq = sw + n * 8;
        #pragma unroll
        for (int q = 0; q < 8; ++q) {
            ulonglong2 wv = wq[q];                // (w2q,w2q),(w2q+1,w2q+1)
            fma2(acc[2 * q    ][0], wv.x, cur.x);
            fma2(acc[2 * q    ][1], wv.x, cur.y);
            fma2(acc[2 * q + 1][0], wv.y, cur.x);
            fma2(acc[2 * q + 1][1], wv.y, cur.y);
        }
    }

    #pragma unroll
    for (int b = 0; b < 16; ++b) {
        float* o = out + (size_t)b * Dn + d;
        red_add4(o, f2lo(acc[b][0]), f2hi(acc[b][0]),
                    f2lo(acc[b][1]), f2hi(acc[b][1]));
    }
}

// ============================================================
extern "C" void kernel_launch(void* const* d_in, const int* in_sizes, int n_in,
                              void* d_out, int out_size) {
    const float* key = (const float*)d_in[0];
    const float* mem = (const float*)d_in[1];
    // metadata order is key, memory; swap defensively if sizes say otherwise
    if (n_in >= 2 && in_sizes[0] == Nn * Dn) {
        key = (const float*)d_in[1];
        mem = (const float*)d_in[0];
    }
    float* out = (float*)d_out;

    // 64KB dynamic smem for k_dots (attribute persists from the harness's
    // non-captured correctness call, so capture-time behavior is identical)
    const int kdots_smem = KSTG * 4096 * (int)sizeof(float);
    cudaFuncSetAttribute(k_dots, cudaFuncAttributeMaxDynamicSharedMemorySize,
                         kdots_smem);

    k_dots<<<dim3(125, DSPLIT), 256, kdots_smem>>>(key, mem);
    k_softmax<<<16, 256>>>(out);   // also zeroes out before k_read's red.adds
    k_read<<<dim3(49, 12), 128>>>(mem, out);
}